// round 1
// baseline (speedup 1.0000x reference)
#include <cuda_runtime.h>
#include <math.h>

#define BB   4
#define SEQ  1024
#define EMB  1024
#define NH   16
#define HD   64
#define DFF  4096
#define MROWS (BB*SEQ)   // 4096

// ---------------- scratch (static device globals; no allocation) ----------------
__device__ float g_nx [MROWS*EMB];
__device__ float g_q  [MROWS*EMB];
__device__ float g_k  [MROWS*EMB];
__device__ float g_v  [MROWS*EMB];
__device__ float g_o  [MROWS*EMB];
__device__ float g_x1 [MROWS*EMB];
__device__ float g_nx2[MROWS*EMB];
__device__ float g_h  [MROWS*DFF];
__device__ float g_s  [(size_t)BB*NH*SEQ*SEQ];   // 256 MB attention scores

// ---------------- LayerNorm (one block per row of 1024) ----------------
__global__ __launch_bounds__(256)
void layernorm_k(const float* __restrict__ x, const float* __restrict__ g,
                 const float* __restrict__ b, float* __restrict__ out)
{
    __shared__ float red[8];
    const int row = blockIdx.x;
    const int tid = threadIdx.x;
    const float* xr = x + (size_t)row * EMB;

    float4 f = reinterpret_cast<const float4*>(xr)[tid];

    // mean
    float s = f.x + f.y + f.z + f.w;
    #pragma unroll
    for (int o = 16; o > 0; o >>= 1) s += __shfl_xor_sync(0xffffffffu, s, o);
    if ((tid & 31) == 0) red[tid >> 5] = s;
    __syncthreads();
    float mean = 0.f;
    #pragma unroll
    for (int i = 0; i < 8; i++) mean += red[i];
    mean *= (1.0f / (float)EMB);
    __syncthreads();

    // variance (ddof=1)
    float dx0 = f.x - mean, dx1 = f.y - mean, dx2 = f.z - mean, dx3 = f.w - mean;
    float ss = dx0*dx0 + dx1*dx1 + dx2*dx2 + dx3*dx3;
    #pragma unroll
    for (int o = 16; o > 0; o >>= 1) ss += __shfl_xor_sync(0xffffffffu, ss, o);
    if ((tid & 31) == 0) red[tid >> 5] = ss;
    __syncthreads();
    float var = 0.f;
    #pragma unroll
    for (int i = 0; i < 8; i++) var += red[i];
    var *= (1.0f / (float)(EMB - 1));
    const float rs = 1.0f / (sqrtf(var) + 1e-8f);

    const float4 gg = reinterpret_cast<const float4*>(g)[tid];
    const float4 bb = reinterpret_cast<const float4*>(b)[tid];
    float4 r;
    r.x = gg.x * dx0 * rs + bb.x;
    r.y = gg.y * dx1 * rs + bb.y;
    r.z = gg.z * dx2 * rs + bb.z;
    r.w = gg.w * dx3 * rs + bb.w;
    reinterpret_cast<float4*>(out + (size_t)row * EMB)[tid] = r;
}

// ---------------- GELU ----------------
__device__ __forceinline__ float gelu_f(float x) {
    const float c = 0.7978845608028654f;  // sqrt(2/pi)
    float t = tanhf(c * (x + 0.044715f * x * x * x));
    return 0.5f * x * (1.0f + t);
}

// ---------------- GEMM: C = epi(A @ W^T + bias) [+ residual] ----------------
// A[M,K] row-major, W[N,K] row-major. BM=BN=128, BK=16, 256 thr, 8x8/thread.
// Smem tiles stored transposed [BK][BM] for conflict-free float4 frag loads.
template <int EPI>   // 0 = none, 1 = gelu
__global__ __launch_bounds__(256)
void gemm_nt(const float* __restrict__ A, const float* __restrict__ W,
             const float* __restrict__ bias, const float* __restrict__ res,
             float* __restrict__ C, int M, int N, int K)
{
    __shared__ float As[16][128];
    __shared__ float Ws[16][128];

    const int tid = threadIdx.x;
    const int tx = tid & 15;        // col group
    const int ty = tid >> 4;        // row group
    const int bm = blockIdx.y * 128;
    const int bn = blockIdx.x * 128;

    const float* Ap = A + (size_t)bm * K;
    const float* Wp = W + (size_t)bn * K;

    float acc[8][8];
    #pragma unroll
    for (int i = 0; i < 8; i++)
        #pragma unroll
        for (int j = 0; j < 8; j++) acc[i][j] = 0.f;

    for (int k0 = 0; k0 < K; k0 += 16) {
        #pragma unroll
        for (int l = 0; l < 2; l++) {
            int vidx = tid + l * 256;        // 0..511
            int r  = vidx >> 2;              // 0..127
            int c  = (vidx & 3) << 2;        // 0,4,8,12
            float4 fa = *reinterpret_cast<const float4*>(Ap + (size_t)r * K + k0 + c);
            As[c+0][r] = fa.x; As[c+1][r] = fa.y; As[c+2][r] = fa.z; As[c+3][r] = fa.w;
            float4 fw = *reinterpret_cast<const float4*>(Wp + (size_t)r * K + k0 + c);
            Ws[c+0][r] = fw.x; Ws[c+1][r] = fw.y; Ws[c+2][r] = fw.z; Ws[c+3][r] = fw.w;
        }
        __syncthreads();

        #pragma unroll
        for (int kk = 0; kk < 16; kk++) {
            float4 a0 = *reinterpret_cast<float4*>(&As[kk][ty * 8]);
            float4 a1 = *reinterpret_cast<float4*>(&As[kk][ty * 8 + 4]);
            float4 b0 = *reinterpret_cast<float4*>(&Ws[kk][tx * 8]);
            float4 b1 = *reinterpret_cast<float4*>(&Ws[kk][tx * 8 + 4]);
            float av[8] = {a0.x, a0.y, a0.z, a0.w, a1.x, a1.y, a1.z, a1.w};
            float bv[8] = {b0.x, b0.y, b0.z, b0.w, b1.x, b1.y, b1.z, b1.w};
            #pragma unroll
            for (int i = 0; i < 8; i++)
                #pragma unroll
                for (int j = 0; j < 8; j++)
                    acc[i][j] += av[i] * bv[j];
        }
        __syncthreads();
    }

    #pragma unroll
    for (int i = 0; i < 8; i++) {
        int row = bm + ty * 8 + i;
        #pragma unroll
        for (int j = 0; j < 8; j++) {
            int col = bn + tx * 8 + j;
            float vv = acc[i][j] + bias[col];
            if (EPI == 1) vv = gelu_f(vv);
            if (res) vv += res[(size_t)row * N + col];
            C[(size_t)row * N + col] = vv;
        }
    }
}

// ---------------- Attention scores: S = mask(Q K^T / 8) ----------------
// grid: (ktile, qtile, b*h); block 256; 64x64 tile, 4x4 per thread.
__global__ __launch_bounds__(256)
void attn_scores_k(const float* __restrict__ q, const float* __restrict__ k,
                   const int* __restrict__ mask, float* __restrict__ s)
{
    __shared__ float Qs[64][64];  // [d][row]
    __shared__ float Ks[64][64];  // [d][row]

    const int bh = blockIdx.z;
    const int b  = bh >> 4;
    const int h  = bh & 15;
    const int qbase = blockIdx.y * 64;
    const int kbase = blockIdx.x * 64;
    const int tid = threadIdx.x;
    const int tx = tid & 15, ty = tid >> 4;

    #pragma unroll
    for (int l = 0; l < 4; l++) {
        int vidx = tid + l * 256;            // 0..1023
        int r  = vidx >> 4;                  // 0..63
        int c4 = (vidx & 15) << 2;           // 0..60
        float4 fq = *reinterpret_cast<const float4*>(
            q + ((size_t)(b * SEQ + qbase + r)) * EMB + h * HD + c4);
        Qs[c4+0][r] = fq.x; Qs[c4+1][r] = fq.y; Qs[c4+2][r] = fq.z; Qs[c4+3][r] = fq.w;
        float4 fk = *reinterpret_cast<const float4*>(
            k + ((size_t)(b * SEQ + kbase + r)) * EMB + h * HD + c4);
        Ks[c4+0][r] = fk.x; Ks[c4+1][r] = fk.y; Ks[c4+2][r] = fk.z; Ks[c4+3][r] = fk.w;
    }
    __syncthreads();

    float acc[4][4];
    #pragma unroll
    for (int i = 0; i < 4; i++)
        #pragma unroll
        for (int j = 0; j < 4; j++) acc[i][j] = 0.f;

    #pragma unroll
    for (int d = 0; d < 64; d++) {
        float4 a = *reinterpret_cast<float4*>(&Qs[d][ty * 4]);
        float4 bb = *reinterpret_cast<float4*>(&Ks[d][tx * 4]);
        float av[4] = {a.x, a.y, a.z, a.w};
        float bv[4] = {bb.x, bb.y, bb.z, bb.w};
        #pragma unroll
        for (int i = 0; i < 4; i++)
            #pragma unroll
            for (int j = 0; j < 4; j++)
                acc[i][j] += av[i] * bv[j];
    }

    #pragma unroll
    for (int i = 0; i < 4; i++) {
        int qi = qbase + ty * 4 + i;
        #pragma unroll
        for (int j = 0; j < 4; j++) {
            int kj = kbase + tx * 4 + j;
            int m = mask[((size_t)b * SEQ + qi) * SEQ + kj];
            float val = (m == 0) ? -0.01f : acc[i][j] * 0.125f;
            s[((size_t)bh * SEQ + qi) * SEQ + kj] = val;
        }
    }
}

// ---------------- Softmax over rows of 1024, in place ----------------
__global__ __launch_bounds__(256)
void softmax_k(float* __restrict__ s)
{
    __shared__ float red[8];
    const size_t row = blockIdx.x;
    const int tid = threadIdx.x;
    float* p = s + row * (size_t)SEQ;

    float4 f = reinterpret_cast<float4*>(p)[tid];
    float m = fmaxf(fmaxf(f.x, f.y), fmaxf(f.z, f.w));
    #pragma unroll
    for (int o = 16; o > 0; o >>= 1) m = fmaxf(m, __shfl_xor_sync(0xffffffffu, m, o));
    if ((tid & 31) == 0) red[tid >> 5] = m;
    __syncthreads();
    float mx = red[0];
    #pragma unroll
    for (int i = 1; i < 8; i++) mx = fmaxf(mx, red[i]);
    __syncthreads();

    f.x = expf(f.x - mx); f.y = expf(f.y - mx);
    f.z = expf(f.z - mx); f.w = expf(f.w - mx);
    float sm = f.x + f.y + f.z + f.w;
    #pragma unroll
    for (int o = 16; o > 0; o >>= 1) sm += __shfl_xor_sync(0xffffffffu, sm, o);
    if ((tid & 31) == 0) red[tid >> 5] = sm;
    __syncthreads();
    float tot = 0.f;
    #pragma unroll
    for (int i = 0; i < 8; i++) tot += red[i];
    float inv = 1.0f / tot;

    f.x *= inv; f.y *= inv; f.z *= inv; f.w *= inv;
    reinterpret_cast<float4*>(p)[tid] = f;
}

// ---------------- O = P @ V per (b,h) ----------------
// grid: (qtile, b*h); block 256; C tile 64(q) x 64(d), 4x4 per thread.
__global__ __launch_bounds__(256)
void attn_pv_k(const float* __restrict__ s, const float* __restrict__ v,
               float* __restrict__ o)
{
    __shared__ float Ps[64][64];  // [k][q]
    __shared__ float Vs[64][64];  // [k][d]

    const int bh = blockIdx.y;
    const int b  = bh >> 4;
    const int h  = bh & 15;
    const int qbase = blockIdx.x * 64;
    const int tid = threadIdx.x;
    const int tx = tid & 15, ty = tid >> 4;

    float acc[4][4];
    #pragma unroll
    for (int i = 0; i < 4; i++)
        #pragma unroll
        for (int j = 0; j < 4; j++) acc[i][j] = 0.f;

    for (int kt = 0; kt < SEQ / 64; kt++) {
        #pragma unroll
        for (int l = 0; l < 4; l++) {
            int vidx = tid + l * 256;
            int r  = vidx >> 4;
            int c4 = (vidx & 15) << 2;
            float4 fp = *reinterpret_cast<const float4*>(
                s + ((size_t)bh * SEQ + qbase + r) * SEQ + kt * 64 + c4);
            Ps[c4+0][r] = fp.x; Ps[c4+1][r] = fp.y; Ps[c4+2][r] = fp.z; Ps[c4+3][r] = fp.w;
            float4 fv = *reinterpret_cast<const float4*>(
                v + ((size_t)(b * SEQ + kt * 64 + r)) * EMB + h * HD + c4);
            *reinterpret_cast<float4*>(&Vs[r][c4]) = fv;
        }
        __syncthreads();

        #pragma unroll
        for (int kk = 0; kk < 64; kk++) {
            float4 a = *reinterpret_cast<float4*>(&Ps[kk][ty * 4]);
            float4 bb = *reinterpret_cast<float4*>(&Vs[kk][tx * 4]);
            float av[4] = {a.x, a.y, a.z, a.w};
            float bv[4] = {bb.x, bb.y, bb.z, bb.w};
            #pragma unroll
            for (int i = 0; i < 4; i++)
                #pragma unroll
                for (int j = 0; j < 4; j++)
                    acc[i][j] += av[i] * bv[j];
        }
        __syncthreads();
    }

    #pragma unroll
    for (int i = 0; i < 4; i++) {
        int qi = qbase + ty * 4 + i;
        #pragma unroll
        for (int j = 0; j < 4; j++) {
            int dj = tx * 4 + j;
            o[((size_t)(b * SEQ + qi)) * EMB + h * HD + dj] = acc[i][j];
        }
    }
}

// ---------------- launch ----------------
extern "C" void kernel_launch(void* const* d_in, const int* in_sizes, int n_in,
                              void* d_out, int out_size)
{
    const float* x   = (const float*)d_in[0];
    const int*   mask= (const int*)  d_in[1];
    const float* Wq  = (const float*)d_in[2];
    const float* bq  = (const float*)d_in[3];
    const float* Wk  = (const float*)d_in[4];
    const float* bk  = (const float*)d_in[5];
    const float* Wv  = (const float*)d_in[6];
    const float* bv  = (const float*)d_in[7];
    const float* Wo  = (const float*)d_in[8];
    const float* bo  = (const float*)d_in[9];
    const float* W1  = (const float*)d_in[10];
    const float* b1  = (const float*)d_in[11];
    const float* W2  = (const float*)d_in[12];
    const float* b2  = (const float*)d_in[13];
    const float* g1  = (const float*)d_in[14];
    const float* be1 = (const float*)d_in[15];
    const float* g2  = (const float*)d_in[16];
    const float* be2 = (const float*)d_in[17];
    float* out = (float*)d_out;

    float *nx, *q, *k, *v, *o, *x1, *nx2, *hbuf, *sbuf;
    cudaGetSymbolAddress((void**)&nx,   g_nx);
    cudaGetSymbolAddress((void**)&q,    g_q);
    cudaGetSymbolAddress((void**)&k,    g_k);
    cudaGetSymbolAddress((void**)&v,    g_v);
    cudaGetSymbolAddress((void**)&o,    g_o);
    cudaGetSymbolAddress((void**)&x1,   g_x1);
    cudaGetSymbolAddress((void**)&nx2,  g_nx2);
    cudaGetSymbolAddress((void**)&hbuf, g_h);
    cudaGetSymbolAddress((void**)&sbuf, g_s);

    const dim3 gEE(EMB / 128, MROWS / 128);   // N=1024 GEMMs
    const dim3 gFF(DFF / 128, MROWS / 128);   // N=4096 GEMM

    // LN1
    layernorm_k<<<MROWS, 256>>>(x, g1, be1, nx);
    // QKV projections
    gemm_nt<0><<<gEE, 256>>>(nx, Wq, bq, nullptr, q, MROWS, EMB, EMB);
    gemm_nt<0><<<gEE, 256>>>(nx, Wk, bk, nullptr, k, MROWS, EMB, EMB);
    gemm_nt<0><<<gEE, 256>>>(nx, Wv, bv, nullptr, v, MROWS, EMB, EMB);
    // attention
    attn_scores_k<<<dim3(SEQ / 64, SEQ / 64, BB * NH), 256>>>(q, k, mask, sbuf);
    softmax_k<<<BB * NH * SEQ, 256>>>(sbuf);
    attn_pv_k<<<dim3(SEQ / 64, BB * NH), 256>>>(sbuf, v, o);
    // out projection + residual
    gemm_nt<0><<<gEE, 256>>>(o, Wo, bo, x, x1, MROWS, EMB, EMB);
    // LN2
    layernorm_k<<<MROWS, 256>>>(x1, g2, be2, nx2);
    // FF1 with GELU
    gemm_nt<1><<<gFF, 256>>>(nx2, W1, b1, nullptr, hbuf, MROWS, DFF, EMB);
    // FF2 + residual -> out
    gemm_nt<0><<<gEE, 256>>>(hbuf, W2, b2, x1, out, MROWS, EMB, DFF);
}

// round 2
// speedup vs baseline: 1.7262x; 1.7262x over previous
#include <cuda_runtime.h>
#include <math.h>
#include <stdint.h>

#define BB   4
#define SEQ  1024
#define EMB  1024
#define NH   16
#define HD   64
#define DFF  4096
#define MROWS (BB*SEQ)   // 4096

// ---------------- scratch (static device globals; no allocation) ----------------
__device__ float g_nx [MROWS*EMB];
__device__ float g_q  [MROWS*EMB];
__device__ float g_k  [MROWS*EMB];
__device__ float g_v  [MROWS*EMB];
__device__ float g_o  [MROWS*EMB];
__device__ float g_x1 [MROWS*EMB];
__device__ float g_nx2[MROWS*EMB];
__device__ float g_h  [MROWS*DFF];
__device__ float g_s  [(size_t)BB*NH*SEQ*SEQ];   // 256 MB attention scores

// ---------------- LayerNorm (one block per row of 1024) ----------------
__global__ __launch_bounds__(256)
void layernorm_k(const float* __restrict__ x, const float* __restrict__ g,
                 const float* __restrict__ b, float* __restrict__ out)
{
    __shared__ float red[8];
    const int row = blockIdx.x;
    const int tid = threadIdx.x;
    const float* xr = x + (size_t)row * EMB;

    float4 f = reinterpret_cast<const float4*>(xr)[tid];

    float s = f.x + f.y + f.z + f.w;
    #pragma unroll
    for (int o = 16; o > 0; o >>= 1) s += __shfl_xor_sync(0xffffffffu, s, o);
    if ((tid & 31) == 0) red[tid >> 5] = s;
    __syncthreads();
    float mean = 0.f;
    #pragma unroll
    for (int i = 0; i < 8; i++) mean += red[i];
    mean *= (1.0f / (float)EMB);
    __syncthreads();

    float dx0 = f.x - mean, dx1 = f.y - mean, dx2 = f.z - mean, dx3 = f.w - mean;
    float ss = dx0*dx0 + dx1*dx1 + dx2*dx2 + dx3*dx3;
    #pragma unroll
    for (int o = 16; o > 0; o >>= 1) ss += __shfl_xor_sync(0xffffffffu, ss, o);
    if ((tid & 31) == 0) red[tid >> 5] = ss;
    __syncthreads();
    float var = 0.f;
    #pragma unroll
    for (int i = 0; i < 8; i++) var += red[i];
    var *= (1.0f / (float)(EMB - 1));
    const float rs = 1.0f / (sqrtf(var) + 1e-8f);

    const float4 gg = reinterpret_cast<const float4*>(g)[tid];
    const float4 bb = reinterpret_cast<const float4*>(b)[tid];
    float4 r;
    r.x = gg.x * dx0 * rs + bb.x;
    r.y = gg.y * dx1 * rs + bb.y;
    r.z = gg.z * dx2 * rs + bb.z;
    r.w = gg.w * dx3 * rs + bb.w;
    reinterpret_cast<float4*>(out + (size_t)row * EMB)[tid] = r;
}

// ---------------- GELU ----------------
__device__ __forceinline__ float gelu_f(float x) {
    const float c = 0.7978845608028654f;  // sqrt(2/pi)
    float t = tanhf(c * (x + 0.044715f * x * x * x));
    return 0.5f * x * (1.0f + t);
}

// ---------------- tf32 helpers ----------------
__device__ __forceinline__ uint32_t f2tf32(float f) {
    uint32_t u;
    asm("cvt.rna.tf32.f32 %0, %1;" : "=r"(u) : "f"(f));
    return u;
}

__device__ __forceinline__ void mma_tf32(float c[4], const uint32_t a[4], const uint32_t b[2]) {
    asm volatile(
        "mma.sync.aligned.m16n8k8.row.col.f32.tf32.tf32.f32 "
        "{%0,%1,%2,%3},{%4,%5,%6,%7},{%8,%9},{%0,%1,%2,%3};"
        : "+f"(c[0]), "+f"(c[1]), "+f"(c[2]), "+f"(c[3])
        : "r"(a[0]), "r"(a[1]), "r"(a[2]), "r"(a[3]), "r"(b[0]), "r"(b[1]));
}

// ---------------- tf32 tensor-core GEMM ----------------
// C = epi(A @ W^T + bias) [+ residual]
// A[M,K] row-major, W[N,K] row-major. BM=BN=128, BK=32.
// 256 threads = 8 warps (2 M x 4 N), warp tile 64x32 (4 m16-frags x 4 n8-frags).
// Smem holds tf32-converted tiles in *fragment order*:
//   As[kstep][m16][lane][4] -> a0..a3 as one uint4 per lane (conflict-free LDS.128)
//   Bs[kstep][n8 ][lane][2] -> b0..b1 as one uint2 per lane (conflict-free LDS.64)
template <int EPI>   // 0 = none, 1 = gelu
__global__ __launch_bounds__(256)
void gemm_tc(const float* __restrict__ A, const float* __restrict__ W,
             const float* __restrict__ bias, const float* __restrict__ res,
             float* __restrict__ C, int M, int N, int K)
{
    __shared__ uint32_t As[4][8][32][4];   // 16 KB
    __shared__ uint32_t Bs[4][16][32][2];  // 16 KB

    const int tid = threadIdx.x;
    const int lane = tid & 31;
    const int wid = tid >> 5;
    const int warpM = wid >> 2;   // 0..1
    const int warpN = wid & 3;    // 0..3
    const int bm = blockIdx.y * 128;
    const int bn = blockIdx.x * 128;

    float acc[4][4][4];
    #pragma unroll
    for (int i = 0; i < 4; i++)
        #pragma unroll
        for (int j = 0; j < 4; j++)
            #pragma unroll
            for (int r = 0; r < 4; r++) acc[i][j][r] = 0.f;

    // per-thread staging coordinates: float4 id f = tid + l*256 (l = 0..3)
    //   A:  m = f>>3 (0..127), kbase = (f&7)*4
    //   W:  n = f>>3,          kbase = (f&7)*4
    float4 ra[4], rb[4];
    const int nk = K >> 5;

    // prologue: prefetch tile 0
    #pragma unroll
    for (int l = 0; l < 4; l++) {
        int f = tid + l * 256;
        int r = f >> 3, kb = (f & 7) << 2;
        ra[l] = *reinterpret_cast<const float4*>(A + (size_t)(bm + r) * K + kb);
        rb[l] = *reinterpret_cast<const float4*>(W + (size_t)(bn + r) * K + kb);
    }

    for (int kt = 0; kt < nk; kt++) {
        __syncthreads();
        // scatter-store current tile (fp32 -> tf32) into fragment-order smem
        #pragma unroll
        for (int l = 0; l < 4; l++) {
            int f = tid + l * 256;
            int m = f >> 3, kb = (f & 7) << 2;
            int kstep = kb >> 3;
            int k4 = (kb >> 2) & 1;
            float av[4] = {ra[l].x, ra[l].y, ra[l].z, ra[l].w};
            float bv[4] = {rb[l].x, rb[l].y, rb[l].z, rb[l].w};
            int aidx = ((m >> 3) & 1) + (k4 << 1);
            int bidx = k4;
            #pragma unroll
            for (int c = 0; c < 4; c++) {
                int ln = ((m & 7) << 2) | c;
                As[kstep][m >> 4][ln][aidx] = f2tf32(av[c]);
                Bs[kstep][m >> 3][ln][bidx] = f2tf32(bv[c]);
            }
        }
        __syncthreads();

        // prefetch next tile
        if (kt + 1 < nk) {
            int k0 = (kt + 1) << 5;
            #pragma unroll
            for (int l = 0; l < 4; l++) {
                int f = tid + l * 256;
                int r = f >> 3, kb = (f & 7) << 2;
                ra[l] = *reinterpret_cast<const float4*>(A + (size_t)(bm + r) * K + k0 + kb);
                rb[l] = *reinterpret_cast<const float4*>(W + (size_t)(bn + r) * K + k0 + kb);
            }
        }

        // compute 4 k-steps of 8
        #pragma unroll
        for (int ks = 0; ks < 4; ks++) {
            uint32_t afrag[4][4];
            uint32_t bfrag[4][2];
            #pragma unroll
            for (int i = 0; i < 4; i++) {
                uint4 v = *reinterpret_cast<const uint4*>(&As[ks][warpM * 4 + i][lane][0]);
                afrag[i][0] = v.x; afrag[i][1] = v.y; afrag[i][2] = v.z; afrag[i][3] = v.w;
            }
            #pragma unroll
            for (int j = 0; j < 4; j++) {
                uint2 v = *reinterpret_cast<const uint2*>(&Bs[ks][warpN * 4 + j][lane][0]);
                bfrag[j][0] = v.x; bfrag[j][1] = v.y;
            }
            #pragma unroll
            for (int i = 0; i < 4; i++)
                #pragma unroll
                for (int j = 0; j < 4; j++)
                    mma_tf32(acc[i][j], afrag[i], bfrag[j]);
        }
    }

    // epilogue: c0,c1 -> (row, col..col+1), c2,c3 -> (row+8, col..col+1)
    const int gid = lane >> 2;       // 0..7
    const int tig = lane & 3;        // 0..3
    #pragma unroll
    for (int i = 0; i < 4; i++) {
        int row0 = bm + warpM * 64 + i * 16 + gid;
        #pragma unroll
        for (int j = 0; j < 4; j++) {
            int col = bn + warpN * 32 + j * 8 + tig * 2;
            float b0 = bias[col], b1 = bias[col + 1];
            float v0 = acc[i][j][0] + b0;
            float v1 = acc[i][j][1] + b1;
            float v2 = acc[i][j][2] + b0;
            float v3 = acc[i][j][3] + b1;
            if (EPI == 1) { v0 = gelu_f(v0); v1 = gelu_f(v1); v2 = gelu_f(v2); v3 = gelu_f(v3); }
            if (res) {
                v0 += res[(size_t)row0 * N + col];
                v1 += res[(size_t)row0 * N + col + 1];
                v2 += res[(size_t)(row0 + 8) * N + col];
                v3 += res[(size_t)(row0 + 8) * N + col + 1];
            }
            *reinterpret_cast<float2*>(C + (size_t)row0 * N + col)       = make_float2(v0, v1);
            *reinterpret_cast<float2*>(C + (size_t)(row0 + 8) * N + col) = make_float2(v2, v3);
        }
    }
}

// ---------------- Attention scores: S = mask(Q K^T / 8) ----------------
__global__ __launch_bounds__(256)
void attn_scores_k(const float* __restrict__ q, const float* __restrict__ k,
                   const int* __restrict__ mask, float* __restrict__ s)
{
    __shared__ float Qs[64][64];  // [d][row]
    __shared__ float Ks[64][64];  // [d][row]

    const int bh = blockIdx.z;
    const int b  = bh >> 4;
    const int h  = bh & 15;
    const int qbase = blockIdx.y * 64;
    const int kbase = blockIdx.x * 64;
    const int tid = threadIdx.x;
    const int tx = tid & 15, ty = tid >> 4;

    #pragma unroll
    for (int l = 0; l < 4; l++) {
        int vidx = tid + l * 256;
        int r  = vidx >> 4;
        int c4 = (vidx & 15) << 2;
        float4 fq = *reinterpret_cast<const float4*>(
            q + ((size_t)(b * SEQ + qbase + r)) * EMB + h * HD + c4);
        Qs[c4+0][r] = fq.x; Qs[c4+1][r] = fq.y; Qs[c4+2][r] = fq.z; Qs[c4+3][r] = fq.w;
        float4 fk = *reinterpret_cast<const float4*>(
            k + ((size_t)(b * SEQ + kbase + r)) * EMB + h * HD + c4);
        Ks[c4+0][r] = fk.x; Ks[c4+1][r] = fk.y; Ks[c4+2][r] = fk.z; Ks[c4+3][r] = fk.w;
    }
    __syncthreads();

    float acc[4][4];
    #pragma unroll
    for (int i = 0; i < 4; i++)
        #pragma unroll
        for (int j = 0; j < 4; j++) acc[i][j] = 0.f;

    #pragma unroll
    for (int d = 0; d < 64; d++) {
        float4 a = *reinterpret_cast<float4*>(&Qs[d][ty * 4]);
        float4 bb = *reinterpret_cast<float4*>(&Ks[d][tx * 4]);
        float av[4] = {a.x, a.y, a.z, a.w};
        float bv[4] = {bb.x, bb.y, bb.z, bb.w};
        #pragma unroll
        for (int i = 0; i < 4; i++)
            #pragma unroll
            for (int j = 0; j < 4; j++)
                acc[i][j] += av[i] * bv[j];
    }

    #pragma unroll
    for (int i = 0; i < 4; i++) {
        int qi = qbase + ty * 4 + i;
        #pragma unroll
        for (int j = 0; j < 4; j++) {
            int kj = kbase + tx * 4 + j;
            int m = mask[((size_t)b * SEQ + qi) * SEQ + kj];
            float val = (m == 0) ? -0.01f : acc[i][j] * 0.125f;
            s[((size_t)bh * SEQ + qi) * SEQ + kj] = val;
        }
    }
}

// ---------------- Softmax over rows of 1024, in place ----------------
__global__ __launch_bounds__(256)
void softmax_k(float* __restrict__ s)
{
    __shared__ float red[8];
    const size_t row = blockIdx.x;
    const int tid = threadIdx.x;
    float* p = s + row * (size_t)SEQ;

    float4 f = reinterpret_cast<float4*>(p)[tid];
    float m = fmaxf(fmaxf(f.x, f.y), fmaxf(f.z, f.w));
    #pragma unroll
    for (int o = 16; o > 0; o >>= 1) m = fmaxf(m, __shfl_xor_sync(0xffffffffu, m, o));
    if ((tid & 31) == 0) red[tid >> 5] = m;
    __syncthreads();
    float mx = red[0];
    #pragma unroll
    for (int i = 1; i < 8; i++) mx = fmaxf(mx, red[i]);
    __syncthreads();

    f.x = expf(f.x - mx); f.y = expf(f.y - mx);
    f.z = expf(f.z - mx); f.w = expf(f.w - mx);
    float sm = f.x + f.y + f.z + f.w;
    #pragma unroll
    for (int o = 16; o > 0; o >>= 1) sm += __shfl_xor_sync(0xffffffffu, sm, o);
    if ((tid & 31) == 0) red[tid >> 5] = sm;
    __syncthreads();
    float tot = 0.f;
    #pragma unroll
    for (int i = 0; i < 8; i++) tot += red[i];
    float inv = 1.0f / tot;

    f.x *= inv; f.y *= inv; f.z *= inv; f.w *= inv;
    reinterpret_cast<float4*>(p)[tid] = f;
}

// ---------------- O = P @ V per (b,h) ----------------
__global__ __launch_bounds__(256)
void attn_pv_k(const float* __restrict__ s, const float* __restrict__ v,
               float* __restrict__ o)
{
    __shared__ float Ps[64][64];  // [k][q]
    __shared__ float Vs[64][64];  // [k][d]

    const int bh = blockIdx.y;
    const int b  = bh >> 4;
    const int h  = bh & 15;
    const int qbase = blockIdx.x * 64;
    const int tid = threadIdx.x;
    const int tx = tid & 15, ty = tid >> 4;

    float acc[4][4];
    #pragma unroll
    for (int i = 0; i < 4; i++)
        #pragma unroll
        for (int j = 0; j < 4; j++) acc[i][j] = 0.f;

    for (int kt = 0; kt < SEQ / 64; kt++) {
        #pragma unroll
        for (int l = 0; l < 4; l++) {
            int vidx = tid + l * 256;
            int r  = vidx >> 4;
            int c4 = (vidx & 15) << 2;
            float4 fp = *reinterpret_cast<const float4*>(
                s + ((size_t)bh * SEQ + qbase + r) * SEQ + kt * 64 + c4);
            Ps[c4+0][r] = fp.x; Ps[c4+1][r] = fp.y; Ps[c4+2][r] = fp.z; Ps[c4+3][r] = fp.w;
            float4 fv = *reinterpret_cast<const float4*>(
                v + ((size_t)(b * SEQ + kt * 64 + r)) * EMB + h * HD + c4);
            *reinterpret_cast<float4*>(&Vs[r][c4]) = fv;
        }
        __syncthreads();

        #pragma unroll
        for (int kk = 0; kk < 64; kk++) {
            float4 a = *reinterpret_cast<float4*>(&Ps[kk][ty * 4]);
            float4 bb = *reinterpret_cast<float4*>(&Vs[kk][tx * 4]);
            float av[4] = {a.x, a.y, a.z, a.w};
            float bv[4] = {bb.x, bb.y, bb.z, bb.w};
            #pragma unroll
            for (int i = 0; i < 4; i++)
                #pragma unroll
                for (int j = 0; j < 4; j++)
                    acc[i][j] += av[i] * bv[j];
        }
        __syncthreads();
    }

    #pragma unroll
    for (int i = 0; i < 4; i++) {
        int qi = qbase + ty * 4 + i;
        #pragma unroll
        for (int j = 0; j < 4; j++) {
            int dj = tx * 4 + j;
            o[((size_t)(b * SEQ + qi)) * EMB + h * HD + dj] = acc[i][j];
        }
    }
}

// ---------------- launch ----------------
extern "C" void kernel_launch(void* const* d_in, const int* in_sizes, int n_in,
                              void* d_out, int out_size)
{
    const float* x   = (const float*)d_in[0];
    const int*   mask= (const int*)  d_in[1];
    const float* Wq  = (const float*)d_in[2];
    const float* bq  = (const float*)d_in[3];
    const float* Wk  = (const float*)d_in[4];
    const float* bk  = (const float*)d_in[5];
    const float* Wv  = (const float*)d_in[6];
    const float* bv  = (const float*)d_in[7];
    const float* Wo  = (const float*)d_in[8];
    const float* bo  = (const float*)d_in[9];
    const float* W1  = (const float*)d_in[10];
    const float* b1  = (const float*)d_in[11];
    const float* W2  = (const float*)d_in[12];
    const float* b2  = (const float*)d_in[13];
    const float* g1  = (const float*)d_in[14];
    const float* be1 = (const float*)d_in[15];
    const float* g2  = (const float*)d_in[16];
    const float* be2 = (const float*)d_in[17];
    float* out = (float*)d_out;

    float *nx, *q, *k, *v, *o, *x1, *nx2, *hbuf, *sbuf;
    cudaGetSymbolAddress((void**)&nx,   g_nx);
    cudaGetSymbolAddress((void**)&q,    g_q);
    cudaGetSymbolAddress((void**)&k,    g_k);
    cudaGetSymbolAddress((void**)&v,    g_v);
    cudaGetSymbolAddress((void**)&o,    g_o);
    cudaGetSymbolAddress((void**)&x1,   g_x1);
    cudaGetSymbolAddress((void**)&nx2,  g_nx2);
    cudaGetSymbolAddress((void**)&hbuf, g_h);
    cudaGetSymbolAddress((void**)&sbuf, g_s);

    const dim3 gEE(EMB / 128, MROWS / 128);   // N=1024 GEMMs
    const dim3 gFF(DFF / 128, MROWS / 128);   // N=4096 GEMM

    // LN1
    layernorm_k<<<MROWS, 256>>>(x, g1, be1, nx);
    // QKV projections (tf32 tensor cores)
    gemm_tc<0><<<gEE, 256>>>(nx, Wq, bq, nullptr, q, MROWS, EMB, EMB);
    gemm_tc<0><<<gEE, 256>>>(nx, Wk, bk, nullptr, k, MROWS, EMB, EMB);
    gemm_tc<0><<<gEE, 256>>>(nx, Wv, bv, nullptr, v, MROWS, EMB, EMB);
    // attention
    attn_scores_k<<<dim3(SEQ / 64, SEQ / 64, BB * NH), 256>>>(q, k, mask, sbuf);
    softmax_k<<<BB * NH * SEQ, 256>>>(sbuf);
    attn_pv_k<<<dim3(SEQ / 64, BB * NH), 256>>>(sbuf, v, o);
    // out projection + residual
    gemm_tc<0><<<gEE, 256>>>(o, Wo, bo, x, x1, MROWS, EMB, EMB);
    // LN2
    layernorm_k<<<MROWS, 256>>>(x1, g2, be2, nx2);
    // FF1 with GELU
    gemm_tc<1><<<gFF, 256>>>(nx2, W1, b1, nullptr, hbuf, MROWS, DFF, EMB);
    // FF2 + residual -> out
    gemm_tc<0><<<gEE, 256>>>(hbuf, W2, b2, x1, out, MROWS, EMB, DFF);
}

// round 5
// speedup vs baseline: 2.9690x; 1.7199x over previous
#include <cuda_runtime.h>
#include <math.h>
#include <stdint.h>

#define BB   4
#define SEQ  1024
#define EMB  1024
#define NH   16
#define HD   64
#define DFF  4096
#define MROWS (BB*SEQ)   // 4096

// ---------------- scratch (static device globals; no allocation) ----------------
__device__ float g_nx [MROWS*EMB];
__device__ float g_q  [MROWS*EMB];
__device__ float g_k  [MROWS*EMB];
__device__ float g_v  [MROWS*EMB];
__device__ float g_vt [BB*NH*HD*SEQ];            // V transposed per head: [bh][d][seq]
__device__ float g_o  [MROWS*EMB];
__device__ float g_x1 [MROWS*EMB];
__device__ float g_nx2[MROWS*EMB];
__device__ float g_h  [MROWS*DFF];
__device__ float g_s  [(size_t)BB*NH*SEQ*SEQ];   // 256 MB attention scores

// ---------------- helpers ----------------
__device__ __forceinline__ uint32_t f2tf32(float f) {
    uint32_t u;
    asm("cvt.rna.tf32.f32 %0, %1;" : "=r"(u) : "f"(f));
    return u;
}

__device__ __forceinline__ void mma8(float c[4], const uint4& a, uint32_t b0, uint32_t b1) {
    asm volatile(
        "mma.sync.aligned.m16n8k8.row.col.f32.tf32.tf32.f32 "
        "{%0,%1,%2,%3},{%4,%5,%6,%7},{%8,%9},{%0,%1,%2,%3};"
        : "+f"(c[0]), "+f"(c[1]), "+f"(c[2]), "+f"(c[3])
        : "r"(a.x), "r"(a.y), "r"(a.z), "r"(a.w), "r"(b0), "r"(b1));
}

__device__ __forceinline__ float gelu_f(float x) {
    const float c = 0.7978845608028654f;  // sqrt(2/pi)
    float t = tanhf(c * (x + 0.044715f * x * x * x));
    return 0.5f * x * (1.0f + t);
}

// Staging layout constants (conflict-free, see analysis):
// A: Aw[kstep*1028 + m16*128 + (m7*4+c)*4 + (rhalf + 2*k4)]   (4112 words)
// B (16 n8 blocks): Bw[kpair*2120 + n8*132 + (n7*4+c)*4 + (2*(kstep&1)+k4)]  (4240 words)
// B ( 8 n8 blocks): kpair stride 1064  (2128 words)
#define A_WORDS 4112
#define B_WORDS_128 4240
#define B_WORDS_64  2128

// ---------------- LayerNorm (one block per row of 1024) ----------------
__global__ __launch_bounds__(256)
void layernorm_k(const float* __restrict__ x, const float* __restrict__ g,
                 const float* __restrict__ b, float* __restrict__ out)
{
    __shared__ float red[8];
    const int row = blockIdx.x;
    const int tid = threadIdx.x;
    const float* xr = x + (size_t)row * EMB;

    float4 f = reinterpret_cast<const float4*>(xr)[tid];

    float s = f.x + f.y + f.z + f.w;
    #pragma unroll
    for (int o = 16; o > 0; o >>= 1) s += __shfl_xor_sync(0xffffffffu, s, o);
    if ((tid & 31) == 0) red[tid >> 5] = s;
    __syncthreads();
    float mean = 0.f;
    #pragma unroll
    for (int i = 0; i < 8; i++) mean += red[i];
    mean *= (1.0f / (float)EMB);
    __syncthreads();

    float dx0 = f.x - mean, dx1 = f.y - mean, dx2 = f.z - mean, dx3 = f.w - mean;
    float ss = dx0*dx0 + dx1*dx1 + dx2*dx2 + dx3*dx3;
    #pragma unroll
    for (int o = 16; o > 0; o >>= 1) ss += __shfl_xor_sync(0xffffffffu, ss, o);
    if ((tid & 31) == 0) red[tid >> 5] = ss;
    __syncthreads();
    float var = 0.f;
    #pragma unroll
    for (int i = 0; i < 8; i++) var += red[i];
    var *= (1.0f / (float)(EMB - 1));
    const float rs = 1.0f / (sqrtf(var) + 1e-8f);

    const float4 gg = reinterpret_cast<const float4*>(g)[tid];
    const float4 bb = reinterpret_cast<const float4*>(b)[tid];
    float4 r;
    r.x = gg.x * dx0 * rs + bb.x;
    r.y = gg.y * dx1 * rs + bb.y;
    r.z = gg.z * dx2 * rs + bb.z;
    r.w = gg.w * dx3 * rs + bb.w;
    reinterpret_cast<float4*>(out + (size_t)row * EMB)[tid] = r;
}

// ================= tf32 mma.sync GEMM, conflict-free staging =================
// C = epi(A @ W^T + bias) [+ res]; A[M,K], W[N,K] row-major. BM=BN=128, BK=32.
// 8 warps (2M x 4N), warp tile 64x32.
template <int EPI>   // 0 = none, 1 = gelu
__global__ __launch_bounds__(256)
void gemm_tc(const float* __restrict__ A, const float* __restrict__ W,
             const float* __restrict__ bias, const float* __restrict__ res,
             float* __restrict__ C, int M, int N, int K)
{
    __shared__ uint32_t Aw[A_WORDS];
    __shared__ uint32_t Bw[B_WORDS_128];

    const int tid = threadIdx.x;
    const int lane = tid & 31;
    const int wid = tid >> 5;
    const int warpM = wid >> 2, warpN = wid & 3;
    const int bm = blockIdx.y * 128;
    const int bn = blockIdx.x * 128;

    // staging coords
    const int chunk = lane & 7;
    const int kstep = chunk >> 1;
    const int k4 = chunk & 1;
    const int kpair = kstep >> 1;
    const int rbase = (((lane >> 3) & 1)) | ((wid & 3) << 1) | (((lane >> 4) & 1) << 3) | ((wid >> 2) << 4);

    float acc[4][4][4];
    #pragma unroll
    for (int i = 0; i < 4; i++)
        #pragma unroll
        for (int j = 0; j < 4; j++)
            #pragma unroll
            for (int r = 0; r < 4; r++) acc[i][j][r] = 0.f;

    const int nk = K >> 5;
    float4 ra[4], rb[4];

    #pragma unroll
    for (int lp = 0; lp < 4; lp++) {
        int r = rbase + (lp << 5);
        ra[lp] = *reinterpret_cast<const float4*>(A + (size_t)(bm + r) * K + chunk * 4);
        rb[lp] = *reinterpret_cast<const float4*>(W + (size_t)(bn + r) * K + chunk * 4);
    }

    for (int kt = 0; kt < nk; kt++) {
        __syncthreads();
        #pragma unroll
        for (int lp = 0; lp < 4; lp++) {
            int r = rbase + (lp << 5);
            int aIdx = kstep * 1028 + (r >> 4) * 128 + (r & 7) * 16 + ((r >> 3) & 1) + 2 * k4;
            int bIdx = kpair * 2120 + (r >> 3) * 132 + (r & 7) * 16 + 2 * (kstep & 1) + k4;
            float av[4] = {ra[lp].x, ra[lp].y, ra[lp].z, ra[lp].w};
            float bv[4] = {rb[lp].x, rb[lp].y, rb[lp].z, rb[lp].w};
            #pragma unroll
            for (int c = 0; c < 4; c++) {
                Aw[aIdx + 4 * c] = f2tf32(av[c]);
                Bw[bIdx + 4 * c] = f2tf32(bv[c]);
            }
        }
        __syncthreads();

        if (kt + 1 < nk) {
            int k0 = (kt + 1) << 5;
            #pragma unroll
            for (int lp = 0; lp < 4; lp++) {
                int r = rbase + (lp << 5);
                ra[lp] = *reinterpret_cast<const float4*>(A + (size_t)(bm + r) * K + k0 + chunk * 4);
                rb[lp] = *reinterpret_cast<const float4*>(W + (size_t)(bn + r) * K + k0 + chunk * 4);
            }
        }

        uint4 bf[2][4];
        #pragma unroll
        for (int kp = 0; kp < 2; kp++)
            #pragma unroll
            for (int j = 0; j < 4; j++)
                bf[kp][j] = *reinterpret_cast<const uint4*>(&Bw[kp * 2120 + (warpN * 4 + j) * 132 + lane * 4]);

        #pragma unroll
        for (int ks = 0; ks < 4; ks++) {
            uint4 af[4];
            #pragma unroll
            for (int i = 0; i < 4; i++)
                af[i] = *reinterpret_cast<const uint4*>(&Aw[ks * 1028 + (warpM * 4 + i) * 128 + lane * 4]);
            const int kp = ks >> 1, odd = ks & 1;
            #pragma unroll
            for (int i = 0; i < 4; i++)
                #pragma unroll
                for (int j = 0; j < 4; j++) {
                    uint32_t b0 = odd ? bf[kp][j].z : bf[kp][j].x;
                    uint32_t b1 = odd ? bf[kp][j].w : bf[kp][j].y;
                    mma8(acc[i][j], af[i], b0, b1);
                }
        }
    }

    const int gid = lane >> 2, tig = lane & 3;
    #pragma unroll
    for (int i = 0; i < 4; i++) {
        int row0 = bm + warpM * 64 + i * 16 + gid;
        #pragma unroll
        for (int j = 0; j < 4; j++) {
            int col = bn + warpN * 32 + j * 8 + tig * 2;
            float b0 = bias[col], b1 = bias[col + 1];
            float v0 = acc[i][j][0] + b0;
            float v1 = acc[i][j][1] + b1;
            float v2 = acc[i][j][2] + b0;
            float v3 = acc[i][j][3] + b1;
            if (EPI == 1) { v0 = gelu_f(v0); v1 = gelu_f(v1); v2 = gelu_f(v2); v3 = gelu_f(v3); }
            if (res) {
                v0 += res[(size_t)row0 * N + col];
                v1 += res[(size_t)row0 * N + col + 1];
                v2 += res[(size_t)(row0 + 8) * N + col];
                v3 += res[(size_t)(row0 + 8) * N + col + 1];
            }
            *reinterpret_cast<float2*>(C + (size_t)row0 * N + col)       = make_float2(v0, v1);
            *reinterpret_cast<float2*>(C + (size_t)(row0 + 8) * N + col) = make_float2(v2, v3);
        }
    }
}

// ================= tf32 scores: S = mask(Q K^T / 8), 128x128 tile, K=64 =================
__global__ __launch_bounds__(256)
void attn_scores_tc(const float* __restrict__ q, const float* __restrict__ kk,
                    const int* __restrict__ mask, float* __restrict__ s)
{
    __shared__ uint32_t Aw[A_WORDS];
    __shared__ uint32_t Bw[B_WORDS_128];

    const int tid = threadIdx.x;
    const int lane = tid & 31;
    const int wid = tid >> 5;
    const int warpM = wid >> 2, warpN = wid & 3;
    const int bh = blockIdx.z;
    const int b = bh >> 4, h = bh & 15;
    const int bm = blockIdx.y * 128;   // q rows
    const int bn = blockIdx.x * 128;   // k rows

    const int chunk = lane & 7;
    const int kstep = chunk >> 1;
    const int k4 = chunk & 1;
    const int kpair = kstep >> 1;
    const int rbase = (((lane >> 3) & 1)) | ((wid & 3) << 1) | (((lane >> 4) & 1) << 3) | ((wid >> 2) << 4);

    const float* aptr = q  + (size_t)(b * SEQ + bm) * EMB + h * HD;
    const float* bptr = kk + (size_t)(b * SEQ + bn) * EMB + h * HD;

    float acc[4][4][4];
    #pragma unroll
    for (int i = 0; i < 4; i++)
        #pragma unroll
        for (int j = 0; j < 4; j++)
            #pragma unroll
            for (int r = 0; r < 4; r++) acc[i][j][r] = 0.f;

    float4 ra[4], rb[4];
    #pragma unroll
    for (int lp = 0; lp < 4; lp++) {
        int r = rbase + (lp << 5);
        ra[lp] = *reinterpret_cast<const float4*>(aptr + (size_t)r * EMB + chunk * 4);
        rb[lp] = *reinterpret_cast<const float4*>(bptr + (size_t)r * EMB + chunk * 4);
    }

    #pragma unroll
    for (int kt = 0; kt < 2; kt++) {
        __syncthreads();
        #pragma unroll
        for (int lp = 0; lp < 4; lp++) {
            int r = rbase + (lp << 5);
            int aIdx = kstep * 1028 + (r >> 4) * 128 + (r & 7) * 16 + ((r >> 3) & 1) + 2 * k4;
            int bIdx = kpair * 2120 + (r >> 3) * 132 + (r & 7) * 16 + 2 * (kstep & 1) + k4;
            float av[4] = {ra[lp].x, ra[lp].y, ra[lp].z, ra[lp].w};
            float bv[4] = {rb[lp].x, rb[lp].y, rb[lp].z, rb[lp].w};
            #pragma unroll
            for (int c = 0; c < 4; c++) {
                Aw[aIdx + 4 * c] = f2tf32(av[c]);
                Bw[bIdx + 4 * c] = f2tf32(bv[c]);
            }
        }
        __syncthreads();

        if (kt == 0) {
            #pragma unroll
            for (int lp = 0; lp < 4; lp++) {
                int r = rbase + (lp << 5);
                ra[lp] = *reinterpret_cast<const float4*>(aptr + (size_t)r * EMB + 32 + chunk * 4);
                rb[lp] = *reinterpret_cast<const float4*>(bptr + (size_t)r * EMB + 32 + chunk * 4);
            }
        }

        uint4 bf[2][4];
        #pragma unroll
        for (int kp = 0; kp < 2; kp++)
            #pragma unroll
            for (int j = 0; j < 4; j++)
                bf[kp][j] = *reinterpret_cast<const uint4*>(&Bw[kp * 2120 + (warpN * 4 + j) * 132 + lane * 4]);

        #pragma unroll
        for (int ks = 0; ks < 4; ks++) {
            uint4 af[4];
            #pragma unroll
            for (int i = 0; i < 4; i++)
                af[i] = *reinterpret_cast<const uint4*>(&Aw[ks * 1028 + (warpM * 4 + i) * 128 + lane * 4]);
            const int kp = ks >> 1, odd = ks & 1;
            #pragma unroll
            for (int i = 0; i < 4; i++)
                #pragma unroll
                for (int j = 0; j < 4; j++) {
                    uint32_t b0 = odd ? bf[kp][j].z : bf[kp][j].x;
                    uint32_t b1 = odd ? bf[kp][j].w : bf[kp][j].y;
                    mma8(acc[i][j], af[i], b0, b1);
                }
        }
    }

    const int gid = lane >> 2, tig = lane & 3;
    #pragma unroll
    for (int i = 0; i < 4; i++) {
        int row0 = bm + warpM * 64 + i * 16 + gid;
        #pragma unroll
        for (int j = 0; j < 4; j++) {
            int col = bn + warpN * 32 + j * 8 + tig * 2;
            int2 m0 = *reinterpret_cast<const int2*>(&mask[((size_t)b * SEQ + row0) * SEQ + col]);
            int2 m1 = *reinterpret_cast<const int2*>(&mask[((size_t)b * SEQ + row0 + 8) * SEQ + col]);
            float2 o0, o1;
            o0.x = m0.x ? acc[i][j][0] * 0.125f : -0.01f;
            o0.y = m0.y ? acc[i][j][1] * 0.125f : -0.01f;
            o1.x = m1.x ? acc[i][j][2] * 0.125f : -0.01f;
            o1.y = m1.y ? acc[i][j][3] * 0.125f : -0.01f;
            *reinterpret_cast<float2*>(s + ((size_t)bh * SEQ + row0) * SEQ + col)     = o0;
            *reinterpret_cast<float2*>(s + ((size_t)bh * SEQ + row0 + 8) * SEQ + col) = o1;
        }
    }
}

// ================= V transpose per head: vt[bh][d][s] = v[b][s][h*64+d] =================
__global__ __launch_bounds__(256)
void transpose_v_k(const float* __restrict__ v, float* __restrict__ vt)
{
    __shared__ float t[32][33];
    const int bh = blockIdx.z;
    const int b = bh >> 4, h = bh & 15;
    const int s0 = blockIdx.x * 32;
    const int d0 = blockIdx.y * 32;
    const int x = threadIdx.x & 31;
    const int y0 = threadIdx.x >> 5;   // 0..7

    #pragma unroll
    for (int j = 0; j < 4; j++) {
        int sr = y0 + j * 8;
        t[sr][x] = v[((size_t)(b * SEQ + s0 + sr)) * EMB + h * HD + d0 + x];
    }
    __syncthreads();
    #pragma unroll
    for (int j = 0; j < 4; j++) {
        int dr = y0 + j * 8;
        vt[((size_t)bh * HD + d0 + dr) * SEQ + s0 + x] = t[x][dr];
    }
}

// ================= tf32 PV: O = P @ V, 128(q) x 64(d), K=SEQ =================
__global__ __launch_bounds__(256)
void attn_pv_tc(const float* __restrict__ s, const float* __restrict__ vt,
                float* __restrict__ o)
{
    __shared__ uint32_t Aw[A_WORDS];
    __shared__ uint32_t Bw[B_WORDS_64];

    const int tid = threadIdx.x;
    const int lane = tid & 31;
    const int wid = tid >> 5;
    const int warpM = wid >> 2, warpN = wid & 3;   // warp tile 64 x 16
    const int bh = blockIdx.y;
    const int b = bh >> 4, h = bh & 15;
    const int bm = blockIdx.x * 128;

    const int chunk = lane & 7;
    const int kstep = chunk >> 1;
    const int k4 = chunk & 1;
    const int kpair = kstep >> 1;
    const int rbase = (((lane >> 3) & 1)) | ((wid & 3) << 1) | (((lane >> 4) & 1) << 3) | ((wid >> 2) << 4);

    const float* aptr = s + (size_t)bh * SEQ * SEQ + (size_t)bm * SEQ;
    const float* bptr = vt + (size_t)bh * HD * SEQ;

    float acc[4][2][4];
    #pragma unroll
    for (int i = 0; i < 4; i++)
        #pragma unroll
        for (int j = 0; j < 2; j++)
            #pragma unroll
            for (int r = 0; r < 4; r++) acc[i][j][r] = 0.f;

    float4 ra[4], rb[2];
    #pragma unroll
    for (int lp = 0; lp < 4; lp++) {
        int r = rbase + (lp << 5);
        ra[lp] = *reinterpret_cast<const float4*>(aptr + (size_t)r * SEQ + chunk * 4);
    }
    #pragma unroll
    for (int lp = 0; lp < 2; lp++) {
        int r = rbase + (lp << 5);   // 0..63
        rb[lp] = *reinterpret_cast<const float4*>(bptr + (size_t)r * SEQ + chunk * 4);
    }

    for (int kt = 0; kt < SEQ / 32; kt++) {
        __syncthreads();
        #pragma unroll
        for (int lp = 0; lp < 4; lp++) {
            int r = rbase + (lp << 5);
            int aIdx = kstep * 1028 + (r >> 4) * 128 + (r & 7) * 16 + ((r >> 3) & 1) + 2 * k4;
            float av[4] = {ra[lp].x, ra[lp].y, ra[lp].z, ra[lp].w};
            #pragma unroll
            for (int c = 0; c < 4; c++) Aw[aIdx + 4 * c] = f2tf32(av[c]);
        }
        #pragma unroll
        for (int lp = 0; lp < 2; lp++) {
            int r = rbase + (lp << 5);
            int bIdx = kpair * 1064 + (r >> 3) * 132 + (r & 7) * 16 + 2 * (kstep & 1) + k4;
            float bv[4] = {rb[lp].x, rb[lp].y, rb[lp].z, rb[lp].w};
            #pragma unroll
            for (int c = 0; c < 4; c++) Bw[bIdx + 4 * c] = f2tf32(bv[c]);
        }
        __syncthreads();

        if (kt + 1 < SEQ / 32) {
            int k0 = (kt + 1) << 5;
            #pragma unroll
            for (int lp = 0; lp < 4; lp++) {
                int r = rbase + (lp << 5);
                ra[lp] = *reinterpret_cast<const float4*>(aptr + (size_t)r * SEQ + k0 + chunk * 4);
            }
            #pragma unroll
            for (int lp = 0; lp < 2; lp++) {
                int r = rbase + (lp << 5);
                rb[lp] = *reinterpret_cast<const float4*>(bptr + (size_t)r * SEQ + k0 + chunk * 4);
            }
        }

        uint4 bf[2][2];
        #pragma unroll
        for (int kp = 0; kp < 2; kp++)
            #pragma unroll
            for (int j = 0; j < 2; j++)
                bf[kp][j] = *reinterpret_cast<const uint4*>(&Bw[kp * 1064 + (warpN * 2 + j) * 132 + lane * 4]);

        #pragma unroll
        for (int ks = 0; ks < 4; ks++) {
            uint4 af[4];
            #pragma unroll
            for (int i = 0; i < 4; i++)
                af[i] = *reinterpret_cast<const uint4*>(&Aw[ks * 1028 + (warpM * 4 + i) * 128 + lane * 4]);
            const int kp = ks >> 1, odd = ks & 1;
            #pragma unroll
            for (int i = 0; i < 4; i++)
                #pragma unroll
                for (int j = 0; j < 2; j++) {
                    uint32_t b0 = odd ? bf[kp][j].z : bf[kp][j].x;
                    uint32_t b1 = odd ? bf[kp][j].w : bf[kp][j].y;
                    mma8(acc[i][j], af[i], b0, b1);
                }
        }
    }

    const int gid = lane >> 2, tig = lane & 3;
    #pragma unroll
    for (int i = 0; i < 4; i++) {
        int row0 = bm + warpM * 64 + i * 16 + gid;
        #pragma unroll
        for (int j = 0; j < 2; j++) {
            int col = warpN * 16 + j * 8 + tig * 2;
            *reinterpret_cast<float2*>(o + ((size_t)(b * SEQ + row0)) * EMB + h * HD + col) =
                make_float2(acc[i][j][0], acc[i][j][1]);
            *reinterpret_cast<float2*>(o + ((size_t)(b * SEQ + row0 + 8)) * EMB + h * HD + col) =
                make_float2(acc[i][j][2], acc[i][j][3]);
        }
    }
}

// ---------------- Softmax over rows of 1024, in place ----------------
__global__ __launch_bounds__(256)
void softmax_k(float* __restrict__ s)
{
    __shared__ float red[8];
    const size_t row = blockIdx.x;
    const int tid = threadIdx.x;
    float* p = s + row * (size_t)SEQ;

    float4 f = reinterpret_cast<float4*>(p)[tid];
    float m = fmaxf(fmaxf(f.x, f.y), fmaxf(f.z, f.w));
    #pragma unroll
    for (int o = 16; o > 0; o >>= 1) m = fmaxf(m, __shfl_xor_sync(0xffffffffu, m, o));
    if ((tid & 31) == 0) red[tid >> 5] = m;
    __syncthreads();
    float mx = red[0];
    #pragma unroll
    for (int i = 1; i < 8; i++) mx = fmaxf(mx, red[i]);
    __syncthreads();

    f.x = expf(f.x - mx); f.y = expf(f.y - mx);
    f.z = expf(f.z - mx); f.w = expf(f.w - mx);
    float sm = f.x + f.y + f.z + f.w;
    #pragma unroll
    for (int o = 16; o > 0; o >>= 1) sm += __shfl_xor_sync(0xffffffffu, sm, o);
    if ((tid & 31) == 0) red[tid >> 5] = sm;
    __syncthreads();
    float tot = 0.f;
    #pragma unroll
    for (int i = 0; i < 8; i++) tot += red[i];
    float inv = 1.0f / tot;

    f.x *= inv; f.y *= inv; f.z *= inv; f.w *= inv;
    reinterpret_cast<float4*>(p)[tid] = f;
}

// ---------------- launch ----------------
extern "C" void kernel_launch(void* const* d_in, const int* in_sizes, int n_in,
                              void* d_out, int out_size)
{
    const float* x   = (const float*)d_in[0];
    const int*   mask= (const int*)  d_in[1];
    const float* Wq  = (const float*)d_in[2];
    const float* bq  = (const float*)d_in[3];
    const float* Wk  = (const float*)d_in[4];
    const float* bk  = (const float*)d_in[5];
    const float* Wv  = (const float*)d_in[6];
    const float* bv  = (const float*)d_in[7];
    const float* Wo  = (const float*)d_in[8];
    const float* bo  = (const float*)d_in[9];
    const float* W1  = (const float*)d_in[10];
    const float* b1  = (const float*)d_in[11];
    const float* W2  = (const float*)d_in[12];
    const float* b2  = (const float*)d_in[13];
    const float* g1  = (const float*)d_in[14];
    const float* be1 = (const float*)d_in[15];
    const float* g2  = (const float*)d_in[16];
    const float* be2 = (const float*)d_in[17];
    float* out = (float*)d_out;

    float *nx, *q, *k, *v, *vt, *o, *x1, *nx2, *hbuf, *sbuf;
    cudaGetSymbolAddress((void**)&nx,   g_nx);
    cudaGetSymbolAddress((void**)&q,    g_q);
    cudaGetSymbolAddress((void**)&k,    g_k);
    cudaGetSymbolAddress((void**)&v,    g_v);
    cudaGetSymbolAddress((void**)&vt,   g_vt);
    cudaGetSymbolAddress((void**)&o,    g_o);
    cudaGetSymbolAddress((void**)&x1,   g_x1);
    cudaGetSymbolAddress((void**)&nx2,  g_nx2);
    cudaGetSymbolAddress((void**)&hbuf, g_h);
    cudaGetSymbolAddress((void**)&sbuf, g_s);

    const dim3 gEE(EMB / 128, MROWS / 128);
    const dim3 gFF(DFF / 128, MROWS / 128);

    layernorm_k<<<MROWS, 256>>>(x, g1, be1, nx);
    gemm_tc<0><<<gEE, 256>>>(nx, Wq, bq, nullptr, q, MROWS, EMB, EMB);
    gemm_tc<0><<<gEE, 256>>>(nx, Wk, bk, nullptr, k, MROWS, EMB, EMB);
    gemm_tc<0><<<gEE, 256>>>(nx, Wv, bv, nullptr, v, MROWS, EMB, EMB);

    transpose_v_k<<<dim3(SEQ / 32, HD / 32, BB * NH), 256>>>(v, vt);
    attn_scores_tc<<<dim3(SEQ / 128, SEQ / 128, BB * NH), 256>>>(q, k, mask, sbuf);
    softmax_k<<<BB * NH * SEQ, 256>>>(sbuf);
    attn_pv_tc<<<dim3(SEQ / 128, BB * NH), 256>>>(sbuf, vt, o);

    gemm_tc<0><<<gEE, 256>>>(o, Wo, bo, x, x1, MROWS, EMB, EMB);
    layernorm_k<<<MROWS, 256>>>(x1, g2, be2, nx2);
    gemm_tc<1><<<gFF, 256>>>(nx2, W1, b1, nullptr, hbuf, MROWS, DFF, EMB);
    gemm_tc<0><<<gEE, 256>>>(hbuf, W2, b2, x1, out, MROWS, EMB, DFF);
}